// round 6
// baseline (speedup 1.0000x reference)
#include <cuda_runtime.h>
#include <cuda_bf16.h>

#define NN 100000
#define EE 1600000
#define TOT (EE + NN)
#define HID 64
#define NLAYERS 10
#define SB 98            // scan blocks (98*1024 >= NN)

typedef unsigned long long ull;

// -------- scratch (device globals; no allocation allowed) --------
__device__ int   g_deg[NN];
__device__ float g_dinv[NN];
__device__ int   g_off[NN + 1];
__device__ int   g_cur[NN];
__device__ int   g_bsum[SB];
__device__ int2  g_edges[TOT];          // (src, __float_as_int(norm))
__device__ float g_X[2][(size_t)NN * HID];
__device__ float g_AX[(size_t)NN * HID];
__device__ float g_Wcr[HID * HID];      // -(W_c @ W_r)

// -------- f32x2 helpers --------
__device__ __forceinline__ ull pk(float lo, float hi) {
    ull r; asm("mov.b64 %0, {%1, %2};" : "=l"(r) : "f"(lo), "f"(hi)); return r;
}
__device__ __forceinline__ ull pk2(float v) {
    ull r; asm("mov.b64 %0, {%1, %1};" : "=l"(r) : "f"(v)); return r;
}
__device__ __forceinline__ void fma2(ull& d, ull a, ull b) {
    asm("fma.rn.f32x2 %0, %1, %2, %0;" : "+l"(d) : "l"(a), "l"(b));
}
__device__ __forceinline__ float2 upk(ull v) {
    float2 r; asm("mov.b64 {%0, %1}, %2;" : "=f"(r.x), "=f"(r.y) : "l"(v)); return r;
}

// -------- precompute: degrees / norms / CSR --------
__global__ void k_init() {
    int i = blockIdx.x * blockDim.x + threadIdx.x;
    if (i < NN) g_deg[i] = 1;           // self loop
}

__global__ void k_hist(const int* __restrict__ dst) {
    int e = blockIdx.x * blockDim.x + threadIdx.x;
    if (e < EE) atomicAdd(&g_deg[dst[e]], 1);
}

__global__ void k_dinv() {
    int i = blockIdx.x * blockDim.x + threadIdx.x;
    if (i < NN) g_dinv[i] = rsqrtf((float)g_deg[i]);
}

// phase 1: per-block sums
__global__ void k_scan1() {
    __shared__ int s[32];
    int b = blockIdx.x, t = threadIdx.x, i = b * 1024 + t;
    int v = (i < NN) ? g_deg[i] : 0;
#pragma unroll
    for (int o = 16; o > 0; o >>= 1) v += __shfl_down_sync(~0u, v, o);
    if ((t & 31) == 0) s[t >> 5] = v;
    __syncthreads();
    if (t < 32) {
        int x = s[t];
#pragma unroll
        for (int o = 16; o > 0; o >>= 1) x += __shfl_down_sync(~0u, x, o);
        if (t == 0) g_bsum[b] = x;
    }
}

// phase 2: scan the 98 block sums (trivial)
__global__ void k_scan2() {
    int run = 0;
    for (int b = 0; b < SB; b++) { int v = g_bsum[b]; g_bsum[b] = run; run += v; }
    g_off[NN] = run;
}

// phase 3: block-level exclusive scan + block prefix
__global__ void k_scan3() {
    __shared__ int s[32];
    int b = blockIdx.x, t = threadIdx.x, i = b * 1024 + t;
    int v = (i < NN) ? g_deg[i] : 0;
    int lane = t & 31, wid = t >> 5;
    int incl = v;
#pragma unroll
    for (int o = 1; o < 32; o <<= 1) { int y = __shfl_up_sync(~0u, incl, o); if (lane >= o) incl += y; }
    if (lane == 31) s[wid] = incl;
    __syncthreads();
    if (t < 32) {
        int x = s[t], ix = x;
#pragma unroll
        for (int o = 1; o < 32; o <<= 1) { int y = __shfl_up_sync(~0u, ix, o); if (lane >= o) ix += y; }
        s[t] = ix - x;
    }
    __syncthreads();
    int excl = incl - v + s[wid] + g_bsum[b];
    if (i < NN) { g_off[i] = excl; g_cur[i] = excl; }
}

__global__ void k_fill(const int* __restrict__ src, const int* __restrict__ dst) {
    int i = blockIdx.x * blockDim.x + threadIdx.x;
    if (i >= TOT) return;
    int s, d;
    if (i < EE) { s = src[i]; d = dst[i]; }
    else        { s = i - EE; d = s; }
    int pos = atomicAdd(&g_cur[d], 1);
    float nrm = g_dinv[s] * g_dinv[d];
    g_edges[pos] = make_int2(s, __float_as_int(nrm));
}

// -------- Wcr = -(W_c @ W_r), 64x64, one block --------
__global__ __launch_bounds__(256) void k_wcr(const float* __restrict__ Wc,
                                             const float* __restrict__ Wr) {
    __shared__ float sA[64 * 64];
    __shared__ float sB[64 * 64];
    int tid = threadIdx.x;
    for (int i = tid; i < 1024; i += 256) {
        ((float4*)sA)[i] = ((const float4*)Wc)[i];
        ((float4*)sB)[i] = ((const float4*)Wr)[i];
    }
    __syncthreads();
    int row = tid >> 2, c0 = (tid & 3) * 16;
    float acc[16];
#pragma unroll
    for (int j = 0; j < 16; j++) acc[j] = 0.f;
    for (int k = 0; k < 64; k++) {
        float a = sA[row * 64 + k];
#pragma unroll
        for (int j = 0; j < 16; j++) acc[j] += a * sB[k * 64 + c0 + j];
    }
#pragma unroll
    for (int j = 0; j < 16; j++) g_Wcr[row * 64 + c0 + j] = -acc[j];
}

// -------- X0 = tanh(x @ W_emb + b_emb) --------
__global__ __launch_bounds__(256) void k_embed(const float* __restrict__ Xin,
                                               const float* __restrict__ W,
                                               const float* __restrict__ b) {
    __shared__ float sW[64 * 64];
    __shared__ float sX[64 * 64];
    int tid = threadIdx.x;
    int r0  = blockIdx.x * 64;
    for (int i = tid; i < 1024; i += 256) {
        ((float4*)sW)[i] = ((const float4*)W)[i];
        int row = i >> 4;
        float4 v = (r0 + row < NN) ? ((const float4*)Xin)[(size_t)r0 * 16 + i]
                                   : make_float4(0, 0, 0, 0);
        ((float4*)sX)[i] = v;
    }
    __syncthreads();
    int cg = tid & 15, rg = tid >> 4, row = rg * 4;
    float4 bias = *(const float4*)&b[cg * 4];
    float acc[4][4];
#pragma unroll
    for (int a = 0; a < 4; a++) { acc[a][0] = bias.x; acc[a][1] = bias.y; acc[a][2] = bias.z; acc[a][3] = bias.w; }
#pragma unroll 8
    for (int k = 0; k < 64; k++) {
        float4 w = *(const float4*)&sW[k * 64 + cg * 4];
#pragma unroll
        for (int a = 0; a < 4; a++) {
            float xk = sX[(row + a) * 64 + k];
            acc[a][0] += xk * w.x; acc[a][1] += xk * w.y; acc[a][2] += xk * w.z; acc[a][3] += xk * w.w;
        }
    }
#pragma unroll
    for (int a = 0; a < 4; a++) {
        int r = r0 + row + a;
        if (r < NN) {
            float4 v = make_float4(tanhf(acc[a][0]), tanhf(acc[a][1]), tanhf(acc[a][2]), tanhf(acc[a][3]));
            *(float4*)&g_X[0][(size_t)r * 64 + cg * 4] = v;
        }
    }
}

// -------- AX[v] = sum_{e->v} norm * X[src]  (warp per node) --------
__global__ __launch_bounds__(256) void k_agg(int inbuf) {
    int v = blockIdx.x * 8 + (threadIdx.x >> 5);
    if (v >= NN) return;
    int lane = threadIdx.x & 31;
    const float* __restrict__ X = g_X[inbuf];
    int beg = g_off[v], end = g_off[v + 1];
    float ax = 0.f, ay = 0.f;
    int i = beg;
    for (; i + 1 < end; i += 2) {
        int2 m0 = g_edges[i];
        int2 m1 = g_edges[i + 1];
        float2 x0 = *(const float2*)&X[(size_t)m0.x * 64 + lane * 2];
        float2 x1 = *(const float2*)&X[(size_t)m1.x * 64 + lane * 2];
        float n0 = __int_as_float(m0.y);
        float n1 = __int_as_float(m1.y);
        ax += n0 * x0.x + n1 * x1.x;
        ay += n0 * x0.y + n1 * x1.y;
    }
    if (i < end) {
        int2 m = g_edges[i];
        float2 xv = *(const float2*)&X[(size_t)m.x * 64 + lane * 2];
        float n = __int_as_float(m.y);
        ax += n * xv.x;
        ay += n * xv.y;
    }
    *(float2*)&g_AX[(size_t)v * 64 + lane * 2] = make_float2(ax, ay);
}

// -------- swizzled activation tile loader (64 rows x 64 cols) --------
__device__ __forceinline__ void load_tile_swz(const float* __restrict__ src,
                                              float* sA, int r0, int tid) {
    for (int i = tid; i < 1024; i += 128) {
        int row = i >> 4;
        int c0  = (i & 15) * 4;
        float4 v = (r0 + row < NN) ? *(const float4*)&src[(size_t)(r0 + row) * 64 + c0]
                                   : make_float4(0, 0, 0, 0);
        int swz = ((row >> 2) & 3) << 3;
        *(float4*)&sA[row * 64 + (c0 ^ swz)] = v;
    }
}

// -------- fused step: X' = tanh( (AX)@Wc + X@(-WcWr) + (bc - br) ) --------
// 64 rows/block, 128 threads, thread tile 4 rows x 8 cols, FFMA2.
__global__ __launch_bounds__(128) void k_step(int inbuf, int outbuf,
                                              const float* __restrict__ Wc,
                                              const float* __restrict__ bc,
                                              const float* __restrict__ br) {
    __shared__ float sW1[64 * 64];
    __shared__ float sW2[64 * 64];
    __shared__ float sA[64 * 64];
    int tid = threadIdx.x;
    int r0  = blockIdx.x * 64;

    for (int i = tid; i < 1024; i += 128) {
        ((float4*)sW1)[i] = ((const float4*)Wc)[i];
        ((float4*)sW2)[i] = ((const float4*)g_Wcr)[i];
    }
    load_tile_swz(g_AX, sA, r0, tid);

    int cg = tid & 7, rg = tid >> 3;
    int row = rg * 4;
    int swz = (rg & 3) << 3;

    ull acc[4][4];
#pragma unroll
    for (int p = 0; p < 4; p++) {
        int j = cg * 8 + 2 * p;
        ull bv = pk(bc[j] - br[j], bc[j + 1] - br[j + 1]);
        acc[0][p] = bv; acc[1][p] = bv; acc[2][p] = bv; acc[3][p] = bv;
    }
    __syncthreads();

    // phase 1: += AX @ Wc
#pragma unroll 8
    for (int k = 0; k < 64; k++) {
        int kk = k ^ swz;
        ulonglong2 w0 = *(const ulonglong2*)&sW1[k * 64 + cg * 8];
        ulonglong2 w1 = *(const ulonglong2*)&sW1[k * 64 + cg * 8 + 4];
#pragma unroll
        for (int a = 0; a < 4; a++) {
            ull x2 = pk2(sA[(row + a) * 64 + kk]);
            fma2(acc[a][0], x2, w0.x); fma2(acc[a][1], x2, w0.y);
            fma2(acc[a][2], x2, w1.x); fma2(acc[a][3], x2, w1.y);
        }
    }
    __syncthreads();
    load_tile_swz(g_X[inbuf], sA, r0, tid);
    __syncthreads();

    // phase 2: += X @ (-WcWr)
#pragma unroll 8
    for (int k = 0; k < 64; k++) {
        int kk = k ^ swz;
        ulonglong2 w0 = *(const ulonglong2*)&sW2[k * 64 + cg * 8];
        ulonglong2 w1 = *(const ulonglong2*)&sW2[k * 64 + cg * 8 + 4];
#pragma unroll
        for (int a = 0; a < 4; a++) {
            ull x2 = pk2(sA[(row + a) * 64 + kk]);
            fma2(acc[a][0], x2, w0.x); fma2(acc[a][1], x2, w0.y);
            fma2(acc[a][2], x2, w1.x); fma2(acc[a][3], x2, w1.y);
        }
    }

    float* __restrict__ Xo = g_X[outbuf];
#pragma unroll
    for (int a = 0; a < 4; a++) {
        int r = r0 + row + a;
        if (r < NN) {
            float2 f0 = upk(acc[a][0]), f1 = upk(acc[a][1]);
            float2 f2 = upk(acc[a][2]), f3 = upk(acc[a][3]);
            float4 o0 = make_float4(tanhf(f0.x), tanhf(f0.y), tanhf(f1.x), tanhf(f1.y));
            float4 o1 = make_float4(tanhf(f2.x), tanhf(f2.y), tanhf(f3.x), tanhf(f3.y));
            *(float4*)&Xo[(size_t)r * 64 + cg * 8]     = o0;
            *(float4*)&Xo[(size_t)r * 64 + cg * 8 + 4] = o1;
        }
    }
}

// -------- readout: out = lrelu( lrelu(X @ W1 + b1) @ W2 + b2 ) --------
__device__ __forceinline__ float lrelu(float v) { return fmaxf(v, 0.01f * v); }

__global__ __launch_bounds__(128) void k_read(const float* __restrict__ W1,
                                              const float* __restrict__ b1,
                                              const float* __restrict__ W2,
                                              const float* __restrict__ b2,
                                              float* __restrict__ out) {
    __shared__ float sX[64 * 64];
    __shared__ float sW1[64 * 32];
    __shared__ float sW2[32 * 32];
    __shared__ float sH[64 * 32];
    int tid = threadIdx.x;
    int r0  = blockIdx.x * 64;
    const float* Xin = g_X[0];
    for (int i = tid; i < 1024; i += 128) {
        int row = i >> 4;
        float4 v = (r0 + row < NN) ? ((const float4*)Xin)[(size_t)r0 * 16 + i]
                                   : make_float4(0, 0, 0, 0);
        ((float4*)sX)[i] = v;
    }
    for (int i = tid; i < 512; i += 128) ((float4*)sW1)[i] = ((const float4*)W1)[i];
    for (int i = tid; i < 256; i += 128) ((float4*)sW2)[i] = ((const float4*)W2)[i];
    __syncthreads();
    int cg = tid & 7, rg = tid >> 3, row = rg * 4;
    float4 bias = *(const float4*)&b1[cg * 4];
    float acc[4][4];
#pragma unroll
    for (int a = 0; a < 4; a++) { acc[a][0] = bias.x; acc[a][1] = bias.y; acc[a][2] = bias.z; acc[a][3] = bias.w; }
#pragma unroll 8
    for (int k = 0; k < 64; k++) {
        float4 w = *(const float4*)&sW1[k * 32 + cg * 4];
#pragma unroll
        for (int a = 0; a < 4; a++) {
            float xk = sX[(row + a) * 64 + k];
            acc[a][0] += xk * w.x; acc[a][1] += xk * w.y; acc[a][2] += xk * w.z; acc[a][3] += xk * w.w;
        }
    }
#pragma unroll
    for (int a = 0; a < 4; a++) {
        float4 v = make_float4(lrelu(acc[a][0]), lrelu(acc[a][1]), lrelu(acc[a][2]), lrelu(acc[a][3]));
        *(float4*)&sH[(row + a) * 32 + cg * 4] = v;
    }
    __syncthreads();
    float4 bias2 = *(const float4*)&b2[cg * 4];
#pragma unroll
    for (int a = 0; a < 4; a++) { acc[a][0] = bias2.x; acc[a][1] = bias2.y; acc[a][2] = bias2.z; acc[a][3] = bias2.w; }
#pragma unroll
    for (int k = 0; k < 32; k++) {
        float4 w = *(const float4*)&sW2[k * 32 + cg * 4];
#pragma unroll
        for (int a = 0; a < 4; a++) {
            float xk = sH[(row + a) * 32 + k];
            acc[a][0] += xk * w.x; acc[a][1] += xk * w.y; acc[a][2] += xk * w.z; acc[a][3] += xk * w.w;
        }
    }
#pragma unroll
    for (int a = 0; a < 4; a++) {
        int r = r0 + row + a;
        if (r < NN) {
            float4 v = make_float4(lrelu(acc[a][0]), lrelu(acc[a][1]), lrelu(acc[a][2]), lrelu(acc[a][3]));
            *(float4*)&out[(size_t)r * 32 + cg * 4] = v;
        }
    }
}

extern "C" void kernel_launch(void* const* d_in, const int* in_sizes, int n_in,
                              void* d_out, int out_size) {
    const float* x     = (const float*)d_in[0];
    const int*   ei    = (const int*)d_in[1];
    const float* W_emb = (const float*)d_in[2];
    const float* b_emb = (const float*)d_in[3];
    const float* W_c   = (const float*)d_in[4];
    const float* b_c   = (const float*)d_in[5];
    const float* W_r   = (const float*)d_in[6];
    const float* b_r   = (const float*)d_in[7];
    const float* W_1   = (const float*)d_in[8];
    const float* b_1   = (const float*)d_in[9];
    const float* W_2   = (const float*)d_in[10];
    const float* b_2   = (const float*)d_in[11];
    float* out = (float*)d_out;

    const int* src = ei;
    const int* dst = ei + EE;

    k_init<<<(NN + 255) / 256, 256>>>();
    k_hist<<<(EE + 255) / 256, 256>>>(dst);
    k_dinv<<<(NN + 255) / 256, 256>>>();
    k_scan1<<<SB, 1024>>>();
    k_scan2<<<1, 1>>>();
    k_scan3<<<SB, 1024>>>();
    k_fill<<<(TOT + 255) / 256, 256>>>(src, dst);

    k_wcr<<<1, 256>>>(W_c, W_r);

    int gemm_blocks = (NN + 63) / 64;
    k_embed<<<gemm_blocks, 256>>>(x, W_emb, b_emb);

    for (int t = 0; t < NLAYERS; t++) {
        k_agg<<<(NN + 7) / 8, 256>>>(t & 1);
        k_step<<<gemm_blocks, 128>>>(t & 1, (t + 1) & 1, W_c, b_c, b_r);
    }

    k_read<<<gemm_blocks, 128>>>(W_1, b_1, W_2, b_2, out);
}

// round 7
// speedup vs baseline: 1.3262x; 1.3262x over previous
#include <cuda_runtime.h>
#include <cuda_bf16.h>

#define NN 100000
#define EE 1600000
#define TOT (EE + NN)
#define HID 64
#define NLAYERS 10
#define SB 98            // scan blocks (98*1024 >= NN)

// -------- scratch (device globals; no allocation allowed) --------
__device__ int   g_deg[NN];
__device__ float g_dinv[NN];
__device__ int   g_off[NN + 1];
__device__ int   g_cur[NN];
__device__ int   g_bsum[SB];
__device__ int2  g_edges[TOT];          // (src, __float_as_int(norm))
__device__ float g_X[2][(size_t)NN * HID];
__device__ float g_XW[(size_t)NN * HID];
__device__ float g_R[(size_t)NN * HID];

// -------- precompute: degrees / norms / CSR --------
__global__ void k_init() {
    int i = blockIdx.x * blockDim.x + threadIdx.x;
    if (i < NN) g_deg[i] = 1;           // self loop
}

__global__ void k_hist(const int* __restrict__ dst) {
    int e = blockIdx.x * blockDim.x + threadIdx.x;
    if (e < EE) atomicAdd(&g_deg[dst[e]], 1);
}

__global__ void k_dinv() {
    int i = blockIdx.x * blockDim.x + threadIdx.x;
    if (i < NN) g_dinv[i] = rsqrtf((float)g_deg[i]);
}

// phase 1: per-block sums
__global__ void k_scan1() {
    __shared__ int s[32];
    int b = blockIdx.x, t = threadIdx.x, i = b * 1024 + t;
    int v = (i < NN) ? g_deg[i] : 0;
#pragma unroll
    for (int o = 16; o > 0; o >>= 1) v += __shfl_down_sync(~0u, v, o);
    if ((t & 31) == 0) s[t >> 5] = v;
    __syncthreads();
    if (t < 32) {
        int x = s[t];
#pragma unroll
        for (int o = 16; o > 0; o >>= 1) x += __shfl_down_sync(~0u, x, o);
        if (t == 0) g_bsum[b] = x;
    }
}

// phase 2: scan the 98 block sums (trivial)
__global__ void k_scan2() {
    int run = 0;
    for (int b = 0; b < SB; b++) { int v = g_bsum[b]; g_bsum[b] = run; run += v; }
    g_off[NN] = run;
}

// phase 3: block-level exclusive scan + block prefix
__global__ void k_scan3() {
    __shared__ int s[32];
    int b = blockIdx.x, t = threadIdx.x, i = b * 1024 + t;
    int v = (i < NN) ? g_deg[i] : 0;
    int lane = t & 31, wid = t >> 5;
    int incl = v;
#pragma unroll
    for (int o = 1; o < 32; o <<= 1) { int y = __shfl_up_sync(~0u, incl, o); if (lane >= o) incl += y; }
    if (lane == 31) s[wid] = incl;
    __syncthreads();
    if (t < 32) {
        int x = s[t], ix = x;
#pragma unroll
        for (int o = 1; o < 32; o <<= 1) { int y = __shfl_up_sync(~0u, ix, o); if (lane >= o) ix += y; }
        s[t] = ix - x;
    }
    __syncthreads();
    int excl = incl - v + s[wid] + g_bsum[b];
    if (i < NN) { g_off[i] = excl; g_cur[i] = excl; }
}

__global__ void k_fill(const int* __restrict__ src, const int* __restrict__ dst) {
    int i = blockIdx.x * blockDim.x + threadIdx.x;
    if (i >= TOT) return;
    int s, d;
    if (i < EE) { s = src[i]; d = dst[i]; }
    else        { s = i - EE; d = s; }
    int pos = atomicAdd(&g_cur[d], 1);
    float nrm = g_dinv[s] * g_dinv[d];
    g_edges[pos] = make_int2(s, __float_as_int(nrm));
}

// -------- GEMM helpers: block = 64 rows, 256 threads, each thread 4 rows x 4 cols --------

// X0 = tanh(x @ W_emb + b_emb)
__global__ __launch_bounds__(256) void k_embed(const float* __restrict__ Xin,
                                               const float* __restrict__ W,
                                               const float* __restrict__ b) {
    __shared__ float sW[64 * 64];
    __shared__ float sX[64 * 64];
    int tid = threadIdx.x;
    int r0  = blockIdx.x * 64;
    for (int i = tid; i < 1024; i += 256) {
        ((float4*)sW)[i] = ((const float4*)W)[i];
        int row = i >> 4;
        float4 v = (r0 + row < NN) ? ((const float4*)Xin)[(size_t)r0 * 16 + i]
                                   : make_float4(0, 0, 0, 0);
        ((float4*)sX)[i] = v;
    }
    __syncthreads();
    int cg = tid & 15, rg = tid >> 4, row = rg * 4;
    float4 bias = *(const float4*)&b[cg * 4];
    float acc[4][4];
#pragma unroll
    for (int a = 0; a < 4; a++) { acc[a][0] = bias.x; acc[a][1] = bias.y; acc[a][2] = bias.z; acc[a][3] = bias.w; }
#pragma unroll 8
    for (int k = 0; k < 64; k++) {
        float4 w = *(const float4*)&sW[k * 64 + cg * 4];
#pragma unroll
        for (int a = 0; a < 4; a++) {
            float xk = sX[(row + a) * 64 + k];
            acc[a][0] += xk * w.x; acc[a][1] += xk * w.y; acc[a][2] += xk * w.z; acc[a][3] += xk * w.w;
        }
    }
#pragma unroll
    for (int a = 0; a < 4; a++) {
        int r = r0 + row + a;
        if (r < NN) {
            float4 v = make_float4(tanhf(acc[a][0]), tanhf(acc[a][1]), tanhf(acc[a][2]), tanhf(acc[a][3]));
            *(float4*)&g_X[0][(size_t)r * 64 + cg * 4] = v;
        }
    }
}

// XW = X @ W_c ; R = XW @ W_r + b_r
__global__ __launch_bounds__(256) void k_dual(int inbuf,
                                              const float* __restrict__ Wc,
                                              const float* __restrict__ Wr,
                                              const float* __restrict__ br) {
    __shared__ float sW1[64 * 64];
    __shared__ float sW2[64 * 64];
    __shared__ float sX[64 * 64];
    int tid = threadIdx.x;
    int r0  = blockIdx.x * 64;
    const float* Xin = g_X[inbuf];
    for (int i = tid; i < 1024; i += 256) {
        ((float4*)sW1)[i] = ((const float4*)Wc)[i];
        ((float4*)sW2)[i] = ((const float4*)Wr)[i];
        int row = i >> 4;
        float4 v = (r0 + row < NN) ? ((const float4*)Xin)[(size_t)r0 * 16 + i]
                                   : make_float4(0, 0, 0, 0);
        ((float4*)sX)[i] = v;
    }
    __syncthreads();
    int cg = tid & 15, rg = tid >> 4, row = rg * 4;
    float acc[4][4];
#pragma unroll
    for (int a = 0; a < 4; a++) { acc[a][0] = 0.f; acc[a][1] = 0.f; acc[a][2] = 0.f; acc[a][3] = 0.f; }
#pragma unroll 8
    for (int k = 0; k < 64; k++) {
        float4 w = *(const float4*)&sW1[k * 64 + cg * 4];
#pragma unroll
        for (int a = 0; a < 4; a++) {
            float xk = sX[(row + a) * 64 + k];
            acc[a][0] += xk * w.x; acc[a][1] += xk * w.y; acc[a][2] += xk * w.z; acc[a][3] += xk * w.w;
        }
    }
    __syncthreads();
#pragma unroll
    for (int a = 0; a < 4; a++) {
        float4 v = make_float4(acc[a][0], acc[a][1], acc[a][2], acc[a][3]);
        *(float4*)&sX[(row + a) * 64 + cg * 4] = v;
        int r = r0 + row + a;
        if (r < NN) *(float4*)&g_XW[(size_t)r * 64 + cg * 4] = v;
    }
    __syncthreads();
    float4 bias = *(const float4*)&br[cg * 4];
#pragma unroll
    for (int a = 0; a < 4; a++) { acc[a][0] = bias.x; acc[a][1] = bias.y; acc[a][2] = bias.z; acc[a][3] = bias.w; }
#pragma unroll 8
    for (int k = 0; k < 64; k++) {
        float4 w = *(const float4*)&sW2[k * 64 + cg * 4];
#pragma unroll
        for (int a = 0; a < 4; a++) {
            float xk = sX[(row + a) * 64 + k];
            acc[a][0] += xk * w.x; acc[a][1] += xk * w.y; acc[a][2] += xk * w.z; acc[a][3] += xk * w.w;
        }
    }
#pragma unroll
    for (int a = 0; a < 4; a++) {
        int r = r0 + row + a;
        if (r < NN) {
            float4 v = make_float4(acc[a][0], acc[a][1], acc[a][2], acc[a][3]);
            *(float4*)&g_R[(size_t)r * 64 + cg * 4] = v;
        }
    }
}

// Xout = tanh( sum_{e->v} norm * XW[src] + b_c - R[v] )   (warp per node)
__global__ __launch_bounds__(256) void k_agg(const float* __restrict__ bc, int outbuf) {
    int v = blockIdx.x * 8 + (threadIdx.x >> 5);
    if (v >= NN) return;
    int lane = threadIdx.x & 31;
    int beg = g_off[v], end = g_off[v + 1];
    float ax = 0.f, ay = 0.f;
    int i = beg;
    for (; i + 1 < end; i += 2) {
        int2 m0 = g_edges[i];
        int2 m1 = g_edges[i + 1];
        float2 x0 = *(const float2*)&g_XW[(size_t)m0.x * 64 + lane * 2];
        float2 x1 = *(const float2*)&g_XW[(size_t)m1.x * 64 + lane * 2];
        float n0 = __int_as_float(m0.y);
        float n1 = __int_as_float(m1.y);
        ax += n0 * x0.x + n1 * x1.x;
        ay += n0 * x0.y + n1 * x1.y;
    }
    if (i < end) {
        int2 m = g_edges[i];
        float2 xv = *(const float2*)&g_XW[(size_t)m.x * 64 + lane * 2];
        float n = __int_as_float(m.y);
        ax += n * xv.x;
        ay += n * xv.y;
    }
    float2 r = *(const float2*)&g_R[(size_t)v * 64 + lane * 2];
    float2 b = *(const float2*)&bc[lane * 2];
    float2 o = make_float2(tanhf(ax + b.x - r.x), tanhf(ay + b.y - r.y));
    *(float2*)&g_X[outbuf][(size_t)v * 64 + lane * 2] = o;
}

// out = lrelu( lrelu(X @ W1 + b1) @ W2 + b2 )   64 rows/block, 128 threads
__device__ __forceinline__ float lrelu(float v) { return fmaxf(v, 0.01f * v); }

__global__ __launch_bounds__(128) void k_read(const float* __restrict__ W1,
                                              const float* __restrict__ b1,
                                              const float* __restrict__ W2,
                                              const float* __restrict__ b2,
                                              float* __restrict__ out) {
    __shared__ float sX[64 * 64];
    __shared__ float sW1[64 * 32];
    __shared__ float sW2[32 * 32];
    __shared__ float sH[64 * 32];
    int tid = threadIdx.x;
    int r0  = blockIdx.x * 64;
    const float* Xin = g_X[0];
    for (int i = tid; i < 1024; i += 128) {
        int row = i >> 4;
        float4 v = (r0 + row < NN) ? ((const float4*)Xin)[(size_t)r0 * 16 + i]
                                   : make_float4(0, 0, 0, 0);
        ((float4*)sX)[i] = v;
    }
    for (int i = tid; i < 512; i += 128) ((float4*)sW1)[i] = ((const float4*)W1)[i];
    for (int i = tid; i < 256; i += 128) ((float4*)sW2)[i] = ((const float4*)W2)[i];
    __syncthreads();
    int cg = tid & 7, rg = tid >> 3, row = rg * 4;
    float4 bias = *(const float4*)&b1[cg * 4];
    float acc[4][4];
#pragma unroll
    for (int a = 0; a < 4; a++) { acc[a][0] = bias.x; acc[a][1] = bias.y; acc[a][2] = bias.z; acc[a][3] = bias.w; }
#pragma unroll 8
    for (int k = 0; k < 64; k++) {
        float4 w = *(const float4*)&sW1[k * 32 + cg * 4];
#pragma unroll
        for (int a = 0; a < 4; a++) {
            float xk = sX[(row + a) * 64 + k];
            acc[a][0] += xk * w.x; acc[a][1] += xk * w.y; acc[a][2] += xk * w.z; acc[a][3] += xk * w.w;
        }
    }
#pragma unroll
    for (int a = 0; a < 4; a++) {
        float4 v = make_float4(lrelu(acc[a][0]), lrelu(acc[a][1]), lrelu(acc[a][2]), lrelu(acc[a][3]));
        *(float4*)&sH[(row + a) * 32 + cg * 4] = v;
    }
    __syncthreads();
    float4 bias2 = *(const float4*)&b2[cg * 4];
#pragma unroll
    for (int a = 0; a < 4; a++) { acc[a][0] = bias2.x; acc[a][1] = bias2.y; acc[a][2] = bias2.z; acc[a][3] = bias2.w; }
#pragma unroll
    for (int k = 0; k < 32; k++) {
        float4 w = *(const float4*)&sW2[k * 32 + cg * 4];
#pragma unroll
        for (int a = 0; a < 4; a++) {
            float xk = sH[(row + a) * 32 + k];
            acc[a][0] += xk * w.x; acc[a][1] += xk * w.y; acc[a][2] += xk * w.z; acc[a][3] += xk * w.w;
        }
    }
#pragma unroll
    for (int a = 0; a < 4; a++) {
        int r = r0 + row + a;
        if (r < NN) {
            float4 v = make_float4(lrelu(acc[a][0]), lrelu(acc[a][1]), lrelu(acc[a][2]), lrelu(acc[a][3]));
            *(float4*)&out[(size_t)r * 32 + cg * 4] = v;
        }
    }
}

extern "C" void kernel_launch(void* const* d_in, const int* in_sizes, int n_in,
                              void* d_out, int out_size) {
    const float* x     = (const float*)d_in[0];
    const int*   ei    = (const int*)d_in[1];
    const float* W_emb = (const float*)d_in[2];
    const float* b_emb = (const float*)d_in[3];
    const float* W_c   = (const float*)d_in[4];
    const float* b_c   = (const float*)d_in[5];
    const float* W_r   = (const float*)d_in[6];
    const float* b_r   = (const float*)d_in[7];
    const float* W_1   = (const float*)d_in[8];
    const float* b_1   = (const float*)d_in[9];
    const float* W_2   = (const float*)d_in[10];
    const float* b_2   = (const float*)d_in[11];
    float* out = (float*)d_out;

    const int* src = ei;
    const int* dst = ei + EE;

    k_init<<<(NN + 255) / 256, 256>>>();
    k_hist<<<(EE + 255) / 256, 256>>>(dst);
    k_dinv<<<(NN + 255) / 256, 256>>>();
    k_scan1<<<SB, 1024>>>();
    k_scan2<<<1, 1>>>();
    k_scan3<<<SB, 1024>>>();
    k_fill<<<(TOT + 255) / 256, 256>>>(src, dst);

    int gemm_blocks = (NN + 63) / 64;
    k_embed<<<gemm_blocks, 256>>>(x, W_emb, b_emb);

    for (int t = 0; t < NLAYERS; t++) {
        k_dual<<<gemm_blocks, 256>>>(t & 1, W_c, W_r, b_r);
        k_agg<<<(NN + 7) / 8, 256>>>(b_c, (t + 1) & 1);
    }

    k_read<<<gemm_blocks, 128>>>(W_1, b_1, W_2, b_2, out);
}

// round 13
// speedup vs baseline: 1.5498x; 1.1686x over previous
#include <cuda_runtime.h>
#include <cuda_bf16.h>
#include <cstdint>

#define NN 100000
#define EE 1600000
#define TOT (EE + NN)
#define HID 64
#define NLAYERS 10
#define SB 98            // scan blocks (98*1024 >= NN)
#define GB 782           // gemm blocks of 128 rows (782*128 >= NN)
#define KP 72            // padded smem k-stride (bf16 elems): conflict-free LDS

// -------- scratch (device globals; no allocation allowed) --------
__device__ int   g_deg[NN];
__device__ float g_dinv[NN];
__device__ int   g_off[NN + 1];
__device__ int   g_cur[NN];
__device__ int   g_bsum[SB];
__device__ int2  g_edges[TOT];          // (src, __float_as_int(norm))
__device__ float g_X[2][(size_t)NN * HID];
__device__ float g_XW[(size_t)NN * HID];
__device__ float g_G[(size_t)NN * HID];     // X @ (-Wc@Wr)
__device__ float g_Wcr[HID * HID];          // -(W_c @ W_r)
__device__ __nv_bfloat16 g_Bh[128 * 64];    // dual weights^T hi  [n][k]
__device__ __nv_bfloat16 g_Bl[128 * 64];    // dual weights^T lo
__device__ __nv_bfloat16 g_Beh[64 * 64];    // emb weights^T hi
__device__ __nv_bfloat16 g_Bel[64 * 64];    // emb weights^T lo

// ================= mma helper (plain sm_80+ PTX; no 'a' features) =================
__device__ __forceinline__ void mma16816(float* c, uint32_t a0, uint32_t a1, uint32_t a2,
                                         uint32_t a3, uint32_t b0, uint32_t b1) {
    asm volatile("mma.sync.aligned.m16n8k16.row.col.f32.bf16.bf16.f32 "
                 "{%0,%1,%2,%3}, {%4,%5,%6,%7}, {%8,%9}, {%0,%1,%2,%3};"
                 : "+f"(c[0]), "+f"(c[1]), "+f"(c[2]), "+f"(c[3])
                 : "r"(a0), "r"(a1), "r"(a2), "r"(a3), "r"(b0), "r"(b1));
}

// ================= precompute: degrees / norms / CSR =================
__global__ void k_init() {
    int i = blockIdx.x * blockDim.x + threadIdx.x;
    if (i < NN) g_deg[i] = 1;           // self loop
}

__global__ void k_hist(const int* __restrict__ dst) {
    int e = blockIdx.x * blockDim.x + threadIdx.x;
    if (e < EE) atomicAdd(&g_deg[dst[e]], 1);
}

__global__ void k_dinv() {
    int i = blockIdx.x * blockDim.x + threadIdx.x;
    if (i < NN) g_dinv[i] = rsqrtf((float)g_deg[i]);
}

__global__ void k_scan1() {
    __shared__ int s[32];
    int b = blockIdx.x, t = threadIdx.x, i = b * 1024 + t;
    int v = (i < NN) ? g_deg[i] : 0;
#pragma unroll
    for (int o = 16; o > 0; o >>= 1) v += __shfl_down_sync(~0u, v, o);
    if ((t & 31) == 0) s[t >> 5] = v;
    __syncthreads();
    if (t < 32) {
        int x = s[t];
#pragma unroll
        for (int o = 16; o > 0; o >>= 1) x += __shfl_down_sync(~0u, x, o);
        if (t == 0) g_bsum[b] = x;
    }
}

__global__ void k_scan2() {
    int run = 0;
    for (int b = 0; b < SB; b++) { int v = g_bsum[b]; g_bsum[b] = run; run += v; }
    g_off[NN] = run;
}

__global__ void k_scan3() {
    __shared__ int s[32];
    int b = blockIdx.x, t = threadIdx.x, i = b * 1024 + t;
    int v = (i < NN) ? g_deg[i] : 0;
    int lane = t & 31, wid = t >> 5;
    int incl = v;
#pragma unroll
    for (int o = 1; o < 32; o <<= 1) { int y = __shfl_up_sync(~0u, incl, o); if (lane >= o) incl += y; }
    if (lane == 31) s[wid] = incl;
    __syncthreads();
    if (t < 32) {
        int x = s[t], ix = x;
#pragma unroll
        for (int o = 1; o < 32; o <<= 1) { int y = __shfl_up_sync(~0u, ix, o); if (lane >= o) ix += y; }
        s[t] = ix - x;
    }
    __syncthreads();
    int excl = incl - v + s[wid] + g_bsum[b];
    if (i < NN) { g_off[i] = excl; g_cur[i] = excl; }
}

__global__ void k_fill(const int* __restrict__ src, const int* __restrict__ dst) {
    int i = blockIdx.x * blockDim.x + threadIdx.x;
    if (i >= TOT) return;
    int s, d;
    if (i < EE) { s = src[i]; d = dst[i]; }
    else        { s = i - EE; d = s; }
    int pos = atomicAdd(&g_cur[d], 1);
    float nrm = g_dinv[s] * g_dinv[d];
    g_edges[pos] = make_int2(s, __float_as_int(nrm));
}

// ================= weight prep =================
// g_Wcr = -(W_c @ W_r)
__global__ __launch_bounds__(256) void k_wcr(const float* __restrict__ Wc,
                                             const float* __restrict__ Wr) {
    __shared__ float sA[64 * 64];
    __shared__ float sB[64 * 64];
    int tid = threadIdx.x;
    for (int i = tid; i < 1024; i += 256) {
        ((float4*)sA)[i] = ((const float4*)Wc)[i];
        ((float4*)sB)[i] = ((const float4*)Wr)[i];
    }
    __syncthreads();
    int row = tid >> 2, c0 = (tid & 3) * 16;
    float acc[16];
#pragma unroll
    for (int j = 0; j < 16; j++) acc[j] = 0.f;
    for (int k = 0; k < 64; k++) {
        float a = sA[row * 64 + k];
#pragma unroll
        for (int j = 0; j < 16; j++) acc[j] += a * sB[k * 64 + c0 + j];
    }
#pragma unroll
    for (int j = 0; j < 16; j++) g_Wcr[row * 64 + c0 + j] = -acc[j];
}

// dual weights^T: B[n][k] = (n<64 ? Wc[k][n] : Wcr[k][n-64]), bf16 hi/lo, plain [n][64]
__global__ void k_prep_dual(const float* __restrict__ Wc) {
    int i = blockIdx.x * 256 + threadIdx.x;
    if (i >= 128 * 64) return;
    int n = i >> 6, k = i & 63;
    float w = (n < 64) ? Wc[k * 64 + n] : g_Wcr[k * 64 + (n - 64)];
    __nv_bfloat16 h = __float2bfloat16(w);
    g_Bh[i] = h;
    g_Bl[i] = __float2bfloat16(w - __bfloat162float(h));
}

__global__ void k_prep_emb(const float* __restrict__ We) {
    int i = blockIdx.x * 256 + threadIdx.x;
    if (i >= 64 * 64) return;
    int n = i >> 6, k = i & 63;
    float w = We[k * 64 + n];
    __nv_bfloat16 h = __float2bfloat16(w);
    g_Beh[i] = h;
    g_Bel[i] = __float2bfloat16(w - __bfloat162float(h));
}

// ================= HMMA GEMM: D[128 x NT*8] = A[128 x 64] @ B^T, bf16 hi/lo x3 =================
// 256 threads = 8 warps; warp w owns rows [w*16, w*16+16), all N cols.
// ALL device-global buffers are bound INSIDE device code (never passed from host —
// host-side __device__-symbol decay gives the host shadow, which GB300 ATS happily
// reads as zeros).
// MODE 0 (dual):  A = g_X[inbuf], B = g_Bh/g_Bl, cols 0-63 -> g_XW, 64-127 -> g_G.
// MODE 1 (embed): A = Aext (harness x), B = g_Beh/g_Bel, out = tanh(D + bias) -> g_X[0].
template<int NT, int MODE>
__global__ __launch_bounds__(256)
void k_gemm_mma(const float* __restrict__ Aext, int inbuf,
                const float* __restrict__ bias) {
    extern __shared__ char smem[];
    constexpr int ABYTES = 128 * KP * 2;            // 18432
    constexpr int BBYTES = NT * 8 * KP * 2;
    constexpr int OFF_AH = 0;
    constexpr int OFF_AL = OFF_AH + ABYTES;
    constexpr int OFF_BH = OFF_AL + ABYTES;
    constexpr int OFF_BL = OFF_BH + BBYTES;

    const float* __restrict__ A = (MODE == 1) ? Aext : g_X[inbuf];
    const __nv_bfloat16* __restrict__ Bh = (MODE == 1) ? g_Beh : g_Bh;
    const __nv_bfloat16* __restrict__ Bl = (MODE == 1) ? g_Bel : g_Bl;

    int tid = threadIdx.x, w = tid >> 5, lane = tid & 31;
    int r0 = blockIdx.x * 128;

    // ---- A tile: fp32 -> bf16 hi/lo, padded stride KP ----
    for (int c = tid; c < 2048; c += 256) {
        int row = c >> 4, k4 = (c & 15) * 4;
        float4 v = (r0 + row < NN) ? *(const float4*)&A[(size_t)(r0 + row) * 64 + k4]
                                   : make_float4(0, 0, 0, 0);
        __nv_bfloat16 h0 = __float2bfloat16(v.x), h1 = __float2bfloat16(v.y),
                      h2 = __float2bfloat16(v.z), h3 = __float2bfloat16(v.w);
        __nv_bfloat16 l0 = __float2bfloat16(v.x - __bfloat162float(h0));
        __nv_bfloat16 l1 = __float2bfloat16(v.y - __bfloat162float(h1));
        __nv_bfloat16 l2 = __float2bfloat16(v.z - __bfloat162float(h2));
        __nv_bfloat16 l3 = __float2bfloat16(v.w - __bfloat162float(h3));
        uint32_t off = (uint32_t)(row * KP + k4) * 2;
        uint2 ph, pl;
        ph.x = ((uint32_t)__bfloat16_as_ushort(h1) << 16) | __bfloat16_as_ushort(h0);
        ph.y = ((uint32_t)__bfloat16_as_ushort(h3) << 16) | __bfloat16_as_ushort(h2);
        pl.x = ((uint32_t)__bfloat16_as_ushort(l1) << 16) | __bfloat16_as_ushort(l0);
        pl.y = ((uint32_t)__bfloat16_as_ushort(l3) << 16) | __bfloat16_as_ushort(l2);
        *(uint2*)(smem + OFF_AH + off) = ph;
        *(uint2*)(smem + OFF_AL + off) = pl;
    }
    // ---- B tiles: [n][64] global -> [n][KP] smem ----
    for (int i = tid; i < NT * 8 * 8; i += 256) {
        int n = i >> 3, k8 = (i & 7) * 8;
        uint32_t off = (uint32_t)(n * KP + k8) * 2;
        *(uint4*)(smem + OFF_BH + off) = ((const uint4*)Bh)[i];
        *(uint4*)(smem + OFF_BL + off) = ((const uint4*)Bl)[i];
    }
    __syncthreads();

    // documented mma fragment coordinates
    int gid = lane >> 2;          // C row / A row / B col group
    int tig = lane & 3;           // k pair selector
    int tig2 = tig * 2;

    uint32_t arow0 = (uint32_t)(w * 16 + gid) * KP;
    uint32_t arow1 = arow0 + 8 * KP;

    float acc[NT][4];
#pragma unroll
    for (int nt = 0; nt < NT; nt++) {
        if (MODE == 1) {
            int c = nt * 8 + tig2;
            acc[nt][0] = bias[c]; acc[nt][1] = bias[c + 1];
            acc[nt][2] = bias[c]; acc[nt][3] = bias[c + 1];
        } else {
            acc[nt][0] = acc[nt][1] = acc[nt][2] = acc[nt][3] = 0.f;
        }
    }

#pragma unroll
    for (int ks = 0; ks < 4; ks++) {
        uint32_t kb = ks * 16;
        uint32_t ah0 = *(const uint32_t*)(smem + OFF_AH + (arow0 + kb + tig2) * 2);
        uint32_t ah1 = *(const uint32_t*)(smem + OFF_AH + (arow1 + kb + tig2) * 2);
        uint32_t ah2 = *(const uint32_t*)(smem + OFF_AH + (arow0 + kb + 8 + tig2) * 2);
        uint32_t ah3 = *(const uint32_t*)(smem + OFF_AH + (arow1 + kb + 8 + tig2) * 2);
        uint32_t al0 = *(const uint32_t*)(smem + OFF_AL + (arow0 + kb + tig2) * 2);
        uint32_t al1 = *(const uint32_t*)(smem + OFF_AL + (arow1 + kb + tig2) * 2);
        uint32_t al2 = *(const uint32_t*)(smem + OFF_AL + (arow0 + kb + 8 + tig2) * 2);
        uint32_t al3 = *(const uint32_t*)(smem + OFF_AL + (arow1 + kb + 8 + tig2) * 2);
#pragma unroll
        for (int nt = 0; nt < NT; nt++) {
            uint32_t brow = (uint32_t)(nt * 8 + gid) * KP;
            uint32_t bh0 = *(const uint32_t*)(smem + OFF_BH + (brow + kb + tig2) * 2);
            uint32_t bh1 = *(const uint32_t*)(smem + OFF_BH + (brow + kb + 8 + tig2) * 2);
            uint32_t bl0 = *(const uint32_t*)(smem + OFF_BL + (brow + kb + tig2) * 2);
            uint32_t bl1 = *(const uint32_t*)(smem + OFF_BL + (brow + kb + 8 + tig2) * 2);
            mma16816(acc[nt], ah0, ah1, ah2, ah3, bh0, bh1);
            mma16816(acc[nt], ah0, ah1, ah2, ah3, bl0, bl1);
            mma16816(acc[nt], al0, al1, al2, al3, bh0, bh1);
        }
    }

    // ---- epilogue: C rows gid / gid+8, cols tig2, tig2+1 ----
    int r  = r0 + w * 16 + gid;
    int r2 = r + 8;
#pragma unroll
    for (int nt = 0; nt < NT; nt++) {
        int c = nt * 8 + tig2;
        if (MODE == 0) {
            float* d0 = (c < 64) ? &g_XW[(size_t)r  * 64 + c] : &g_G[(size_t)r  * 64 + (c - 64)];
            float* d1 = (c < 64) ? &g_XW[(size_t)r2 * 64 + c] : &g_G[(size_t)r2 * 64 + (c - 64)];
            if (r  < NN) *(float2*)d0 = make_float2(acc[nt][0], acc[nt][1]);
            if (r2 < NN) *(float2*)d1 = make_float2(acc[nt][2], acc[nt][3]);
        } else {
            if (r  < NN) *(float2*)&g_X[0][(size_t)r  * 64 + c] =
                make_float2(tanhf(acc[nt][0]), tanhf(acc[nt][1]));
            if (r2 < NN) *(float2*)&g_X[0][(size_t)r2 * 64 + c] =
                make_float2(tanhf(acc[nt][2]), tanhf(acc[nt][3]));
        }
    }
}

// ================= aggregate: Xout = tanh( sum norm*XW[src] + (bc-br) + G[v] ) =================
__global__ __launch_bounds__(256) void k_agg(const float* __restrict__ bc,
                                             const float* __restrict__ br, int outbuf) {
    int v = blockIdx.x * 8 + (threadIdx.x >> 5);
    if (v >= NN) return;
    int lane = threadIdx.x & 31;
    int beg = g_off[v], end = g_off[v + 1];
    float ax = 0.f, ay = 0.f;
    int i = beg;
    for (; i + 1 < end; i += 2) {
        int2 m0 = g_edges[i];
        int2 m1 = g_edges[i + 1];
        float2 x0 = *(const float2*)&g_XW[(size_t)m0.x * 64 + lane * 2];
        float2 x1 = *(const float2*)&g_XW[(size_t)m1.x * 64 + lane * 2];
        float n0 = __int_as_float(m0.y);
        float n1 = __int_as_float(m1.y);
        ax += n0 * x0.x + n1 * x1.x;
        ay += n0 * x0.y + n1 * x1.y;
    }
    if (i < end) {
        int2 m = g_edges[i];
        float2 xv = *(const float2*)&g_XW[(size_t)m.x * 64 + lane * 2];
        float n = __int_as_float(m.y);
        ax += n * xv.x;
        ay += n * xv.y;
    }
    float2 g = *(const float2*)&g_G[(size_t)v * 64 + lane * 2];
    float b0 = bc[lane * 2]     - br[lane * 2];
    float b1 = bc[lane * 2 + 1] - br[lane * 2 + 1];
    float2 o = make_float2(tanhf(ax + b0 + g.x), tanhf(ay + b1 + g.y));
    *(float2*)&g_X[outbuf][(size_t)v * 64 + lane * 2] = o;
}

// ================= readout =================
__device__ __forceinline__ float lrelu(float v) { return fmaxf(v, 0.01f * v); }

__global__ __launch_bounds__(128) void k_read(const float* __restrict__ W1,
                                              const float* __restrict__ b1,
                                              const float* __restrict__ W2,
                                              const float* __restrict__ b2,
                                              float* __restrict__ out) {
    __shared__ float sX[64 * 64];
    __shared__ float sW1[64 * 32];
    __shared__ float sW2[32 * 32];
    __shared__ float sH[64 * 32];
    int tid = threadIdx.x;
    int r0  = blockIdx.x * 64;
    const float* Xin = g_X[0];
    for (int i = tid; i < 1024; i += 128) {
        int row = i >> 4;
        float4 v = (r0 + row < NN) ? ((const float4*)Xin)[(size_t)r0 * 16 + i]
                                   : make_float4(0, 0, 0, 0);
        ((float4*)sX)[i] = v;
    }
    for (int i = tid; i < 512; i += 128) ((float4*)sW1)[i] = ((const float4*)W1)[i];
    for (int i = tid; i < 256; i += 128) ((float4*)sW2)[i] = ((const float4*)W2)[i];
    __syncthreads();
    int cg = tid & 7, rg = tid >> 3, row = rg * 4;
    float4 bias = *(const float4*)&b1[cg * 4];
    float acc[4][4];
#pragma unroll
    for (int a = 0; a < 4; a++) { acc[a][0] = bias.x; acc[a][1] = bias.y; acc[a][2] = bias.z; acc[a][3] = bias.w; }
#pragma unroll 8
    for (int k = 0; k < 64; k++) {
        float4 wv = *(const float4*)&sW1[k * 32 + cg * 4];
#pragma unroll
        for (int a = 0; a < 4; a++) {
            float xk = sX[(row + a) * 64 + k];
            acc[a][0] += xk * wv.x; acc[a][1] += xk * wv.y; acc[a][2] += xk * wv.z; acc[a][3] += xk * wv.w;
        }
    }
#pragma unroll
    for (int a = 0; a < 4; a++) {
        float4 v = make_float4(lrelu(acc[a][0]), lrelu(acc[a][1]), lrelu(acc[a][2]), lrelu(acc[a][3]));
        *(float4*)&sH[(row + a) * 32 + cg * 4] = v;
    }
    __syncthreads();
    float4 bias2 = *(const float4*)&b2[cg * 4];
#pragma unroll
    for (int a = 0; a < 4; a++) { acc[a][0] = bias2.x; acc[a][1] = bias2.y; acc[a][2] = bias2.z; acc[a][3] = bias2.w; }
#pragma unroll
    for (int k = 0; k < 32; k++) {
        float4 wv = *(const float4*)&sW2[k * 32 + cg * 4];
#pragma unroll
        for (int a = 0; a < 4; a++) {
            float xk = sH[(row + a) * 32 + k];
            acc[a][0] += xk * wv.x; acc[a][1] += xk * wv.y; acc[a][2] += xk * wv.z; acc[a][3] += xk * wv.w;
        }
    }
#pragma unroll
    for (int a = 0; a < 4; a++) {
        int r = r0 + row + a;
        if (r < NN) {
            float4 v = make_float4(lrelu(acc[a][0]), lrelu(acc[a][1]), lrelu(acc[a][2]), lrelu(acc[a][3]));
            *(float4*)&out[(size_t)r * 32 + cg * 4] = v;
        }
    }
}

extern "C" void kernel_launch(void* const* d_in, const int* in_sizes, int n_in,
                              void* d_out, int out_size) {
    const float* x     = (const float*)d_in[0];
    const int*   ei    = (const int*)d_in[1];
    const float* W_emb = (const float*)d_in[2];
    const float* b_emb = (const float*)d_in[3];
    const float* W_c   = (const float*)d_in[4];
    const float* b_c   = (const float*)d_in[5];
    const float* W_r   = (const float*)d_in[6];
    const float* b_r   = (const float*)d_in[7];
    const float* W_1   = (const float*)d_in[8];
    const float* b_1   = (const float*)d_in[9];
    const float* W_2   = (const float*)d_in[10];
    const float* b_2   = (const float*)d_in[11];
    float* out = (float*)d_out;

    const int* src = ei;
    const int* dst = ei + EE;

    constexpr int SMEM_DUAL = 128 * KP * 2 * 2 + 128 * KP * 2 * 2;  // 73728
    constexpr int SMEM_EMB  = 128 * KP * 2 * 2 + 64 * KP * 2 * 2;   // 55296
    cudaFuncSetAttribute(k_gemm_mma<16, 0>, cudaFuncAttributeMaxDynamicSharedMemorySize, SMEM_DUAL);
    cudaFuncSetAttribute(k_gemm_mma<8, 1>,  cudaFuncAttributeMaxDynamicSharedMemorySize, SMEM_EMB);

    k_init<<<(NN + 255) / 256, 256>>>();
    k_hist<<<(EE + 255) / 256, 256>>>(dst);
    k_dinv<<<(NN + 255) / 256, 256>>>();
    k_scan1<<<SB, 1024>>>();
    k_scan2<<<1, 1>>>();
    k_scan3<<<SB, 1024>>>();
    k_fill<<<(TOT + 255) / 256, 256>>>(src, dst);

    k_wcr<<<1, 256>>>(W_c, W_r);
    k_prep_dual<<<(128 * 64 + 255) / 256, 256>>>(W_c);
    k_prep_emb<<<(64 * 64 + 255) / 256, 256>>>(W_emb);

    // X0 = tanh(x @ W_emb + b_emb)  (writes g_X[0] internally)
    k_gemm_mma<8, 1><<<GB, 256, SMEM_EMB>>>(x, 0, b_emb);

    for (int t = 0; t < NLAYERS; t++) {
        // [XW | G] = X @ [Wc | -WcWr]  (reads g_X[t&1], writes g_XW/g_G internally)
        k_gemm_mma<16, 0><<<GB, 256, SMEM_DUAL>>>(nullptr, t & 1, nullptr);
        k_agg<<<(NN + 7) / 8, 256>>>(b_c, b_r, (t + 1) & 1);
    }

    k_read<<<(NN + 63) / 64, 128>>>(W_1, b_1, W_2, b_2, out);
}

// round 14
// speedup vs baseline: 1.6188x; 1.0446x over previous
#include <cuda_runtime.h>
#include <cuda_bf16.h>
#include <cuda_fp16.h>
#include <cstdint>

#define NN 100000
#define EE 1600000
#define TOT (EE + NN)
#define HID 64
#define NLAYERS 10
#define SB 98            // scan blocks (98*1024 >= NN)
#define GB 782           // gemm blocks of 128 rows (782*128 >= NN)
#define KP 72            // padded smem k-stride (bf16 elems): conflict-free LDS

// -------- scratch (device globals; no allocation allowed) --------
__device__ int   g_deg[NN];
__device__ float g_dinv[NN];
__device__ int   g_off[NN + 1];
__device__ int   g_cur[NN];
__device__ int   g_bsum[SB];
__device__ int2  g_edges[TOT];          // (src, __float_as_int(norm))
__device__ float g_X[2][(size_t)NN * HID];
__device__ __half g_XWh[(size_t)NN * HID];  // X @ Wc, fp16 (gathered -> half traffic)
__device__ float g_G[(size_t)NN * HID];     // X @ (-Wc@Wr)
__device__ float g_Wcr[HID * HID];          // -(W_c @ W_r)
__device__ __nv_bfloat16 g_Bh[128 * 64];    // dual weights^T hi  [n][k]
__device__ __nv_bfloat16 g_Bl[128 * 64];    // dual weights^T lo
__device__ __nv_bfloat16 g_Beh[64 * 64];    // emb weights^T hi
__device__ __nv_bfloat16 g_Bel[64 * 64];    // emb weights^T lo

// ================= mma helper (plain sm_80+ PTX; no 'a' features) =================
__device__ __forceinline__ void mma16816(float* c, uint32_t a0, uint32_t a1, uint32_t a2,
                                         uint32_t a3, uint32_t b0, uint32_t b1) {
    asm volatile("mma.sync.aligned.m16n8k16.row.col.f32.bf16.bf16.f32 "
                 "{%0,%1,%2,%3}, {%4,%5,%6,%7}, {%8,%9}, {%0,%1,%2,%3};"
                 : "+f"(c[0]), "+f"(c[1]), "+f"(c[2]), "+f"(c[3])
                 : "r"(a0), "r"(a1), "r"(a2), "r"(a3), "r"(b0), "r"(b1));
}

// ================= precompute: degrees / norms / CSR =================
__global__ void k_init() {
    int i = blockIdx.x * blockDim.x + threadIdx.x;
    if (i < NN) g_deg[i] = 1;           // self loop
}

__global__ void k_hist(const int* __restrict__ dst) {
    int e = blockIdx.x * blockDim.x + threadIdx.x;
    if (e < EE) atomicAdd(&g_deg[dst[e]], 1);
}

__global__ void k_dinv() {
    int i = blockIdx.x * blockDim.x + threadIdx.x;
    if (i < NN) g_dinv[i] = rsqrtf((float)g_deg[i]);
}

__global__ void k_scan1() {
    __shared__ int s[32];
    int b = blockIdx.x, t = threadIdx.x, i = b * 1024 + t;
    int v = (i < NN) ? g_deg[i] : 0;
#pragma unroll
    for (int o = 16; o > 0; o >>= 1) v += __shfl_down_sync(~0u, v, o);
    if ((t & 31) == 0) s[t >> 5] = v;
    __syncthreads();
    if (t < 32) {
        int x = s[t];
#pragma unroll
        for (int o = 16; o > 0; o >>= 1) x += __shfl_down_sync(~0u, x, o);
        if (t == 0) g_bsum[b] = x;
    }
}

__global__ void k_scan2() {
    int run = 0;
    for (int b = 0; b < SB; b++) { int v = g_bsum[b]; g_bsum[b] = run; run += v; }
    g_off[NN] = run;
}

__global__ void k_scan3() {
    __shared__ int s[32];
    int b = blockIdx.x, t = threadIdx.x, i = b * 1024 + t;
    int v = (i < NN) ? g_deg[i] : 0;
    int lane = t & 31, wid = t >> 5;
    int incl = v;
#pragma unroll
    for (int o = 1; o < 32; o <<= 1) { int y = __shfl_up_sync(~0u, incl, o); if (lane >= o) incl += y; }
    if (lane == 31) s[wid] = incl;
    __syncthreads();
    if (t < 32) {
        int x = s[t], ix = x;
#pragma unroll
        for (int o = 1; o < 32; o <<= 1) { int y = __shfl_up_sync(~0u, ix, o); if (lane >= o) ix += y; }
        s[t] = ix - x;
    }
    __syncthreads();
    int excl = incl - v + s[wid] + g_bsum[b];
    if (i < NN) { g_off[i] = excl; g_cur[i] = excl; }
}

__global__ void k_fill(const int* __restrict__ src, const int* __restrict__ dst) {
    int i = blockIdx.x * blockDim.x + threadIdx.x;
    if (i >= TOT) return;
    int s, d;
    if (i < EE) { s = src[i]; d = dst[i]; }
    else        { s = i - EE; d = s; }
    int pos = atomicAdd(&g_cur[d], 1);
    float nrm = g_dinv[s] * g_dinv[d];
    g_edges[pos] = make_int2(s, __float_as_int(nrm));
}

// ================= weight prep =================
// g_Wcr = -(W_c @ W_r)
__global__ __launch_bounds__(256) void k_wcr(const float* __restrict__ Wc,
                                             const float* __restrict__ Wr) {
    __shared__ float sA[64 * 64];
    __shared__ float sB[64 * 64];
    int tid = threadIdx.x;
    for (int i = tid; i < 1024; i += 256) {
        ((float4*)sA)[i] = ((const float4*)Wc)[i];
        ((float4*)sB)[i] = ((const float4*)Wr)[i];
    }
    __syncthreads();
    int row = tid >> 2, c0 = (tid & 3) * 16;
    float acc[16];
#pragma unroll
    for (int j = 0; j < 16; j++) acc[j] = 0.f;
    for (int k = 0; k < 64; k++) {
        float a = sA[row * 64 + k];
#pragma unroll
        for (int j = 0; j < 16; j++) acc[j] += a * sB[k * 64 + c0 + j];
    }
#pragma unroll
    for (int j = 0; j < 16; j++) g_Wcr[row * 64 + c0 + j] = -acc[j];
}

// dual weights^T: B[n][k] = (n<64 ? Wc[k][n] : Wcr[k][n-64]), bf16 hi/lo, plain [n][64]
__global__ void k_prep_dual(const float* __restrict__ Wc) {
    int i = blockIdx.x * 256 + threadIdx.x;
    if (i >= 128 * 64) return;
    int n = i >> 6, k = i & 63;
    float w = (n < 64) ? Wc[k * 64 + n] : g_Wcr[k * 64 + (n - 64)];
    __nv_bfloat16 h = __float2bfloat16(w);
    g_Bh[i] = h;
    g_Bl[i] = __float2bfloat16(w - __bfloat162float(h));
}

__global__ void k_prep_emb(const float* __restrict__ We) {
    int i = blockIdx.x * 256 + threadIdx.x;
    if (i >= 64 * 64) return;
    int n = i >> 6, k = i & 63;
    float w = We[k * 64 + n];
    __nv_bfloat16 h = __float2bfloat16(w);
    g_Beh[i] = h;
    g_Bel[i] = __float2bfloat16(w - __bfloat162float(h));
}

// ================= HMMA GEMM: D[128 x NT*8] = A[128 x 64] @ B^T, bf16 hi/lo x3 =================
// 256 threads = 8 warps; warp w owns rows [w*16, w*16+16), all N cols.
// Device-global buffers bound INSIDE device code (host-side __device__-symbol decay
// gives the host shadow; GB300 ATS reads it as zeros -> silent corruption).
// MODE 0 (dual):  A = g_X[inbuf]; cols 0-63 -> g_XWh (fp16), 64-127 -> g_G (fp32).
// MODE 1 (embed): A = Aext; out = tanh(D + bias) -> g_X[0].
template<int NT, int MODE>
__global__ __launch_bounds__(256)
void k_gemm_mma(const float* __restrict__ Aext, int inbuf,
                const float* __restrict__ bias) {
    extern __shared__ char smem[];
    constexpr int ABYTES = 128 * KP * 2;            // 18432
    constexpr int BBYTES = NT * 8 * KP * 2;
    constexpr int OFF_AH = 0;
    constexpr int OFF_AL = OFF_AH + ABYTES;
    constexpr int OFF_BH = OFF_AL + ABYTES;
    constexpr int OFF_BL = OFF_BH + BBYTES;

    const float* __restrict__ A = (MODE == 1) ? Aext : g_X[inbuf];
    const __nv_bfloat16* __restrict__ Bh = (MODE == 1) ? g_Beh : g_Bh;
    const __nv_bfloat16* __restrict__ Bl = (MODE == 1) ? g_Bel : g_Bl;

    int tid = threadIdx.x, w = tid >> 5, lane = tid & 31;
    int r0 = blockIdx.x * 128;

    // ---- A tile: fp32 -> bf16 hi/lo, padded stride KP ----
    for (int c = tid; c < 2048; c += 256) {
        int row = c >> 4, k4 = (c & 15) * 4;
        float4 v = (r0 + row < NN) ? *(const float4*)&A[(size_t)(r0 + row) * 64 + k4]
                                   : make_float4(0, 0, 0, 0);
        __nv_bfloat16 h0 = __float2bfloat16(v.x), h1 = __float2bfloat16(v.y),
                      h2 = __float2bfloat16(v.z), h3 = __float2bfloat16(v.w);
        __nv_bfloat16 l0 = __float2bfloat16(v.x - __bfloat162float(h0));
        __nv_bfloat16 l1 = __float2bfloat16(v.y - __bfloat162float(h1));
        __nv_bfloat16 l2 = __float2bfloat16(v.z - __bfloat162float(h2));
        __nv_bfloat16 l3 = __float2bfloat16(v.w - __bfloat162float(h3));
        uint32_t off = (uint32_t)(row * KP + k4) * 2;
        uint2 ph, pl;
        ph.x = ((uint32_t)__bfloat16_as_ushort(h1) << 16) | __bfloat16_as_ushort(h0);
        ph.y = ((uint32_t)__bfloat16_as_ushort(h3) << 16) | __bfloat16_as_ushort(h2);
        pl.x = ((uint32_t)__bfloat16_as_ushort(l1) << 16) | __bfloat16_as_ushort(l0);
        pl.y = ((uint32_t)__bfloat16_as_ushort(l3) << 16) | __bfloat16_as_ushort(l2);
        *(uint2*)(smem + OFF_AH + off) = ph;
        *(uint2*)(smem + OFF_AL + off) = pl;
    }
    // ---- B tiles: [n][64] global -> [n][KP] smem ----
    for (int i = tid; i < NT * 8 * 8; i += 256) {
        int n = i >> 3, k8 = (i & 7) * 8;
        uint32_t off = (uint32_t)(n * KP + k8) * 2;
        *(uint4*)(smem + OFF_BH + off) = ((const uint4*)Bh)[i];
        *(uint4*)(smem + OFF_BL + off) = ((const uint4*)Bl)[i];
    }
    __syncthreads();

    // documented mma fragment coordinates
    int gid = lane >> 2;          // C row / A row / B col group
    int tig = lane & 3;           // k pair selector
    int tig2 = tig * 2;

    uint32_t arow0 = (uint32_t)(w * 16 + gid) * KP;
    uint32_t arow1 = arow0 + 8 * KP;

    float acc[NT][4];
#pragma unroll
    for (int nt = 0; nt < NT; nt++) {
        if (MODE == 1) {
            int c = nt * 8 + tig2;
            acc[nt][0] = bias[c]; acc[nt][1] = bias[c + 1];
            acc[nt][2] = bias[c]; acc[nt][3] = bias[c + 1];
        } else {
            acc[nt][0] = acc[nt][1] = acc[nt][2] = acc[nt][3] = 0.f;
        }
    }

#pragma unroll
    for (int ks = 0; ks < 4; ks++) {
        uint32_t kb = ks * 16;
        uint32_t ah0 = *(const uint32_t*)(smem + OFF_AH + (arow0 + kb + tig2) * 2);
        uint32_t ah1 = *(const uint32_t*)(smem + OFF_AH + (arow1 + kb + tig2) * 2);
        uint32_t ah2 = *(const uint32_t*)(smem + OFF_AH + (arow0 + kb + 8 + tig2) * 2);
        uint32_t ah3 = *(const uint32_t*)(smem + OFF_AH + (arow1 + kb + 8 + tig2) * 2);
        uint32_t al0 = *(const uint32_t*)(smem + OFF_AL + (arow0 + kb + tig2) * 2);
        uint32_t al1 = *(const uint32_t*)(smem + OFF_AL + (arow1 + kb + tig2) * 2);
        uint32_t al2 = *(const uint32_t*)(smem + OFF_AL + (arow0 + kb + 8 + tig2) * 2);
        uint32_t al3 = *(const uint32_t*)(smem + OFF_AL + (arow1 + kb + 8 + tig2) * 2);
#pragma unroll
        for (int nt = 0; nt < NT; nt++) {
            uint32_t brow = (uint32_t)(nt * 8 + gid) * KP;
            uint32_t bh0 = *(const uint32_t*)(smem + OFF_BH + (brow + kb + tig2) * 2);
            uint32_t bh1 = *(const uint32_t*)(smem + OFF_BH + (brow + kb + 8 + tig2) * 2);
            uint32_t bl0 = *(const uint32_t*)(smem + OFF_BL + (brow + kb + tig2) * 2);
            uint32_t bl1 = *(const uint32_t*)(smem + OFF_BL + (brow + kb + 8 + tig2) * 2);
            mma16816(acc[nt], ah0, ah1, ah2, ah3, bh0, bh1);
            mma16816(acc[nt], ah0, ah1, ah2, ah3, bl0, bl1);
            mma16816(acc[nt], al0, al1, al2, al3, bh0, bh1);
        }
    }

    // ---- epilogue: C rows gid / gid+8, cols tig2, tig2+1 ----
    int r  = r0 + w * 16 + gid;
    int r2 = r + 8;
#pragma unroll
    for (int nt = 0; nt < NT; nt++) {
        int c = nt * 8 + tig2;
        if (MODE == 0) {
            if (c < 64) {
                if (r  < NN) *(__half2*)&g_XWh[(size_t)r  * 64 + c] =
                    __floats2half2_rn(acc[nt][0], acc[nt][1]);
                if (r2 < NN) *(__half2*)&g_XWh[(size_t)r2 * 64 + c] =
                    __floats2half2_rn(acc[nt][2], acc[nt][3]);
            } else {
                if (r  < NN) *(float2*)&g_G[(size_t)r  * 64 + (c - 64)] =
                    make_float2(acc[nt][0], acc[nt][1]);
                if (r2 < NN) *(float2*)&g_G[(size_t)r2 * 64 + (c - 64)] =
                    make_float2(acc[nt][2], acc[nt][3]);
            }
        } else {
            if (r  < NN) *(float2*)&g_X[0][(size_t)r  * 64 + c] =
                make_float2(tanhf(acc[nt][0]), tanhf(acc[nt][1]));
            if (r2 < NN) *(float2*)&g_X[0][(size_t)r2 * 64 + c] =
                make_float2(tanhf(acc[nt][2]), tanhf(acc[nt][3]));
        }
    }
}

// ================= aggregate: Xout = tanh( sum norm*XWh[src] + (bc-br) + G[v] ) =================
__global__ __launch_bounds__(256) void k_agg(const float* __restrict__ bc,
                                             const float* __restrict__ br, int outbuf) {
    int v = blockIdx.x * 8 + (threadIdx.x >> 5);
    if (v >= NN) return;
    int lane = threadIdx.x & 31;
    int beg = g_off[v], end = g_off[v + 1];
    float ax = 0.f, ay = 0.f;
    int i = beg;
    for (; i + 1 < end; i += 2) {
        int2 m0 = g_edges[i];
        int2 m1 = g_edges[i + 1];
        float2 x0 = __half22float2(*(const __half2*)&g_XWh[(size_t)m0.x * 64 + lane * 2]);
        float2 x1 = __half22float2(*(const __half2*)&g_XWh[(size_t)m1.x * 64 + lane * 2]);
        float n0 = __int_as_float(m0.y);
        float n1 = __int_as_float(m1.y);
        ax += n0 * x0.x + n1 * x1.x;
        ay += n0 * x0.y + n1 * x1.y;
    }
    if (i < end) {
        int2 m = g_edges[i];
        float2 xv = __half22float2(*(const __half2*)&g_XWh[(size_t)m.x * 64 + lane * 2]);
        float n = __int_as_float(m.y);
        ax += n * xv.x;
        ay += n * xv.y;
    }
    float2 g = *(const float2*)&g_G[(size_t)v * 64 + lane * 2];
    float b0 = bc[lane * 2]     - br[lane * 2];
    float b1 = bc[lane * 2 + 1] - br[lane * 2 + 1];
    float2 o = make_float2(tanhf(ax + b0 + g.x), tanhf(ay + b1 + g.y));
    *(float2*)&g_X[outbuf][(size_t)v * 64 + lane * 2] = o;
}

// ================= readout =================
__device__ __forceinline__ float lrelu(float v) { return fmaxf(v, 0.01f * v); }

__global__ __launch_bounds__(128) void k_read(const float* __restrict__ W1,
                                              const float* __restrict__ b1,
                                              const float* __restrict__ W2,
                                              const float* __restrict__ b2,
                                              float* __restrict__ out) {
    __shared__ float sX[64 * 64];
    __shared__ float sW1[64 * 32];
    __shared__ float sW2[32 * 32];
    __shared__ float sH[64 * 32];
    int tid = threadIdx.x;
    int r0  = blockIdx.x * 64;
    const float* Xin = g_X[0];
    for (int i = tid; i < 1024; i += 128) {
        int row = i >> 4;
        float4 v = (r0 + row < NN) ? ((const float4*)Xin)[(size_t)r0 * 16 + i]
                                   : make_float4(0, 0, 0, 0);
        ((float4*)sX)[i] = v;
    }
    for (int i = tid; i < 512; i += 128) ((float4*)sW1)[i] = ((const float4*)W1)[i];
    for (int i = tid; i < 256; i += 128) ((float4*)sW2)[i] = ((const float4*)W2)[i];
    __syncthreads();
    int cg = tid & 7, rg = tid >> 3, row = rg * 4;
    float4 bias = *(const float4*)&b1[cg * 4];
    float acc[4][4];
#pragma unroll
    for (int a = 0; a < 4; a++) { acc[a][0] = bias.x; acc[a][1] = bias.y; acc[a][2] = bias.z; acc[a][3] = bias.w; }
#pragma unroll 8
    for (int k = 0; k < 64; k++) {
        float4 wv = *(const float4*)&sW1[k * 32 + cg * 4];
#pragma unroll
        for (int a = 0; a < 4; a++) {
            float xk = sX[(row + a) * 64 + k];
            acc[a][0] += xk * wv.x; acc[a][1] += xk * wv.y; acc[a][2] += xk * wv.z; acc[a][3] += xk * wv.w;
        }
    }
#pragma unroll
    for (int a = 0; a < 4; a++) {
        float4 v = make_float4(lrelu(acc[a][0]), lrelu(acc[a][1]), lrelu(acc[a][2]), lrelu(acc[a][3]));
        *(float4*)&sH[(row + a) * 32 + cg * 4] = v;
    }
    __syncthreads();
    float4 bias2 = *(const float4*)&b2[cg * 4];
#pragma unroll
    for (int a = 0; a < 4; a++) { acc[a][0] = bias2.x; acc[a][1] = bias2.y; acc[a][2] = bias2.z; acc[a][3] = bias2.w; }
#pragma unroll
    for (int k = 0; k < 32; k++) {
        float4 wv = *(const float4*)&sW2[k * 32 + cg * 4];
#pragma unroll
        for (int a = 0; a < 4; a++) {
            float xk = sH[(row + a) * 32 + k];
            acc[a][0] += xk * wv.x; acc[a][1] += xk * wv.y; acc[a][2] += xk * wv.z; acc[a][3] += xk * wv.w;
        }
    }
#pragma unroll
    for (int a = 0; a < 4; a++) {
        int r = r0 + row + a;
        if (r < NN) {
            float4 v = make_float4(lrelu(acc[a][0]), lrelu(acc[a][1]), lrelu(acc[a][2]), lrelu(acc[a][3]));
            *(float4*)&out[(size_t)r * 32 + cg * 4] = v;
        }
    }
}

extern "C" void kernel_launch(void* const* d_in, const int* in_sizes, int n_in,
                              void* d_out, int out_size) {
    const float* x     = (const float*)d_in[0];
    const int*   ei    = (const int*)d_in[1];
    const float* W_emb = (const float*)d_in[2];
    const float* b_emb = (const float*)d_in[3];
    const float* W_c   = (const float*)d_in[4];
    const float* b_c   = (const float*)d_in[5];
    const float* W_r   = (const float*)d_in[6];
    const float* b_r   = (const float*)d_in[7];
    const float* W_1   = (const float*)d_in[8];
    const float* b_1   = (const float*)d_in[9];
    const float* W_2   = (const float*)d_in[10];
    const float* b_2   = (const float*)d_in[11];
    float* out = (float*)d_out;

    const int* src = ei;
    const int* dst = ei + EE;

    constexpr int SMEM_DUAL = 128 * KP * 2 * 2 + 128 * KP * 2 * 2;  // 73728
    constexpr int SMEM_EMB  = 128 * KP * 2 * 2 + 64 * KP * 2 * 2;   // 55296
    cudaFuncSetAttribute(k_gemm_mma<16, 0>, cudaFuncAttributeMaxDynamicSharedMemorySize, SMEM_DUAL);
    cudaFuncSetAttribute(k_gemm_mma<8, 1>,  cudaFuncAttributeMaxDynamicSharedMemorySize, SMEM_EMB);

    k_init<<<(NN + 255) / 256, 256>>>();
    k_hist<<<(EE + 255) / 256, 256>>>(dst);
    k_dinv<<<(NN + 255) / 256, 256>>>();
    k_scan1<<<SB, 1024>>>();
    k_scan2<<<1, 1>>>();
    k_scan3<<<SB, 1024>>>();
    k_fill<<<(TOT + 255) / 256, 256>>>(src, dst);

    k_wcr<<<1, 256>>>(W_c, W_r);
    k_prep_dual<<<(128 * 64 + 255) / 256, 256>>>(W_c);
    k_prep_emb<<<(64 * 64 + 255) / 256, 256>>>(W_emb);

    // X0 = tanh(x @ W_emb + b_emb)  (writes g_X[0] internally)
    k_gemm_mma<8, 1><<<GB, 256, SMEM_EMB>>>(x, 0, b_emb);

    for (int t = 0; t < NLAYERS; t++) {
        // [XWh | G] = X @ [Wc | -WcWr]  (reads g_X[t&1], writes g_XWh/g_G internally)
        k_gemm_mma<16, 0><<<GB, 256, SMEM_DUAL>>>(nullptr, t & 1, nullptr);
        k_agg<<<(NN + 7) / 8, 256>>>(b_c, b_r, (t + 1) & 1);
    }

    k_read<<<(NN + 63) / 64, 128>>>(W_1, b_1, W_2, b_2, out);
}